// round 7
// baseline (speedup 1.0000x reference)
#include <cuda_runtime.h>
#include <math.h>

#define Dd 2048
#define Hh 1152
#define Kk 64
#define NAa 18
#define Rr 10

// ---------------- scratch (device globals) ----------------------------------
__device__ __align__(16) float d_z[Dd];
__device__ __align__(16) float d_s[Dd];
__device__ __align__(16) float d_u[Hh];
__device__ __align__(16) float d_gpart[4 * Dd];   // Whh_m@h_t + biases
__device__ __align__(16) float d_gact[4 * Dd];    // full manager gate preact
__device__ __align__(16) float d_T[NAa * Dd];     // u_resh @ Wphi
__device__ __align__(16) float d_hsum[Dd];        // sum_r hn_m[r]
__device__ __align__(16) float d_goalsum[Dd];     // sum_{r=1..9} goals[r]
__device__ float d_cosv[Rr];
__device__ float d_wval;

__device__ __forceinline__ float sigm(float x) { return 1.f / (1.f + expf(-x)); }

// warp dot over NIT*32 float4s (lane-strided), result on all lanes
template <int NIT>
__device__ __forceinline__ float wdot(const float4* __restrict__ a,
                                      const float4* __restrict__ b, int lane) {
    float acc = 0.f;
#pragma unroll
    for (int i = 0; i < NIT; i++) {
        float4 x = a[lane + i * 32];
        float4 y = b[lane + i * 32];
        acc = fmaf(x.x, y.x, acc);
        acc = fmaf(x.y, y.y, acc);
        acc = fmaf(x.z, y.z, acc);
        acc = fmaf(x.w, y.w, acc);
    }
#pragma unroll
    for (int o = 16; o; o >>= 1) acc += __shfl_xor_sync(0xffffffffu, acc, o);
    return acc;
}

// block-cooperative copy of N floats (N % 1024 == 0) into smem, 256 threads
__device__ __forceinline__ void stage(float* __restrict__ dst,
                                      const float* __restrict__ src, int n) {
    const float4* s4 = (const float4*)src;
    float4* d4 = (float4*)dst;
    for (int i = threadIdx.x; i < n / 4; i += 256) d4[i] = s4[i];
}

// ---------------- kS: z, s, hsum, goalsum ------------------------------------
// blocks [0,256):   zs in smem; s rows 1/warp; block 0 also writes d_z
// blocks [256,264): hsum
// blocks [264,272): goalsum
__global__ void __launch_bounds__(256)
kS(const float* __restrict__ x, const float* __restrict__ Wp,
   const float* __restrict__ bp, const float* __restrict__ Wms,
   const float* __restrict__ bms, const float* __restrict__ hn_m,
   const float* __restrict__ goals) {
    const int warp = threadIdx.x >> 5, lane = threadIdx.x & 31;
    const int b = blockIdx.x;
    if (b < 256) {
        __shared__ __align__(16) float zs[Dd];
        float x0 = x[0], x1 = x[1];
        for (int i = threadIdx.x; i < Dd; i += 256) {
            float v = fmaf(Wp[2 * i], x0, fmaf(Wp[2 * i + 1], x1, bp[i]));
            zs[i] = fmaxf(v, 0.f);
        }
        __syncthreads();
        if (b == 0)
            for (int i = threadIdx.x; i < Dd; i += 256) d_z[i] = zs[i];
        int row = b * 8 + warp;
        float v = wdot<16>((const float4*)(Wms + (size_t)row * Dd),
                           (const float4*)zs, lane);
        if (!lane) d_s[row] = fmaxf(v + bms[row], 0.f);
    } else if (b < 264) {
        const int i = (b - 256) * 256 + threadIdx.x;
        float a = 0.f;
#pragma unroll
        for (int r = 0; r < Rr; r++) a += hn_m[(size_t)r * Dd + i];
        d_hsum[i] = a;
    } else {
        const int d = (b - 264) * 256 + threadIdx.x;
        float a = 0.f;
#pragma unroll
        for (int r = 1; r < Rr; r++) a += goals[(size_t)r * Dd + d];
        d_goalsum[d] = a;
    }
}

// ---------------- kBig: one uniform streaming wave ---------------------------
// blocks [0,576):      worker gate rows (2 units/block), z+hn_w staged in smem
// blocks [576,1600):   Whh_m rows 8/block, hn_m[tick] staged -> d_gpart
// blocks [1600,2624):  Wih_m rows 8/block, d_s staged -> d_gact
// blocks [2624,2632):  T columns (256 d/block, u in smem, Wphi streamed once)
// block  2632:         cosines r=0..8
// block  2633:         w_value
__global__ void __launch_bounds__(256)
kBig(const float* __restrict__ Wih_w, const float* __restrict__ Whh_w,
     const float* __restrict__ bih_w, const float* __restrict__ bhh_w,
     const float* __restrict__ hn_w, const float* __restrict__ cn_w,
     const float* __restrict__ Whh_m, const float* __restrict__ bih_m,
     const float* __restrict__ bhh_m, const float* __restrict__ hn_m,
     const float* __restrict__ Wih_m, const float* __restrict__ Wphi,
     const float* __restrict__ goals, const float* __restrict__ states,
     const float* __restrict__ Wc, const float* __restrict__ bc,
     const int* __restrict__ tickp) {
    const int tid = threadIdx.x;
    const int warp = tid >> 5, lane = tid & 31;
    const int b = blockIdx.x;
    __shared__ __align__(16) float vec[Dd + Hh];   // 12.8 KB

    if (b < 576) {
        stage(vec, d_z, Dd);
        stage(vec + Dd, hn_w, Hh);
        __syncthreads();
        const int unit = b * 2 + (warp >> 2);
        const int q = warp & 3;
        const int row = unit + q * Hh;
        float a = wdot<16>((const float4*)(Wih_w + (size_t)row * Dd),
                           (const float4*)vec, lane);
        float c = wdot<9>((const float4*)(Whh_w + (size_t)row * Hh),
                          (const float4*)(vec + Dd), lane);
        __shared__ float gsh[8];
        if (!lane) gsh[warp] = a + c + bih_w[row] + bhh_w[row];
        __syncthreads();
        if ((tid & 127) == 0) {
            const int half = tid >> 7;
            const int j = b * 2 + half;
            const float* g = gsh + half * 4;
            float ig = sigm(g[0]), fg = sigm(g[1]);
            float g2 = tanhf(g[2]), og = sigm(g[3]);
            float c2 = fmaf(fg, cn_w[j], ig * g2);
            d_u[j] = og * tanhf(c2);
        }
    } else if (b < 1600) {
        const int tick = *tickp;
        stage(vec, hn_m + (size_t)tick * Dd, Dd);
        __syncthreads();
        const int row = (b - 576) * 8 + warp;
        float v = wdot<16>((const float4*)(Whh_m + (size_t)row * Dd),
                           (const float4*)vec, lane);
        if (!lane) d_gpart[row] = v + bih_m[row] + bhh_m[row];
    } else if (b < 2624) {
        stage(vec, d_s, Dd);
        __syncthreads();
        const int row = (b - 1600) * 8 + warp;
        float v = wdot<16>((const float4*)(Wih_m + (size_t)row * Dd),
                           (const float4*)vec, lane);
        if (!lane) d_gact[row] = v + d_gpart[row];
    } else if (b < 2632) {
        __shared__ float us[NAa * Kk];
        for (int i = tid; i < NAa * Kk; i += 256) us[i] = d_u[i];
        __syncthreads();
        const int d = (b - 2624) * 256 + tid;
        float acc[NAa];
#pragma unroll
        for (int a = 0; a < NAa; a++) acc[a] = 0.f;
        for (int k = 0; k < Kk; k++) {
            float w = Wphi[(size_t)k * Dd + d];
#pragma unroll
            for (int a = 0; a < NAa; a++)
                acc[a] = fmaf(us[a * Kk + k], w, acc[a]);
        }
#pragma unroll
        for (int a = 0; a < NAa; a++) d_T[(size_t)a * Dd + d] = acc[a];
    } else if (b == 2632) {
        for (int r = warp; r < Rr - 1; r += 8) {
            const float* st = states + (size_t)(r + 1) * Dd;
            const float* gl = goals + (size_t)(r + 1) * Dd;
            float num = 0.f, dd = 0.f, gg = 0.f;
            for (int d = lane; d < Dd; d += 32) {
                float diff = d_s[d] - st[d];
                float go = gl[d];
                num = fmaf(diff, go, num);
                dd = fmaf(diff, diff, dd);
                gg = fmaf(go, go, gg);
            }
#pragma unroll
            for (int o = 16; o; o >>= 1) {
                num += __shfl_xor_sync(0xffffffffu, num, o);
                dd += __shfl_xor_sync(0xffffffffu, dd, o);
                gg += __shfl_xor_sync(0xffffffffu, gg, o);
            }
            if (!lane)
                d_cosv[r] = num / (fmaxf(sqrtf(dd), 1e-8f) *
                                   fmaxf(sqrtf(gg), 1e-8f));
        }
    } else {
        __shared__ float red[256];
        float wv = 0.f;
        for (int j = tid; j < Hh; j += 256) wv = fmaf(d_u[j], Wc[j], wv);
        red[tid] = wv;
        __syncthreads();
        for (int s = 128; s; s >>= 1) {
            if (tid < s) red[tid] += red[tid + s];
            __syncthreads();
        }
        if (tid == 0) d_wval = red[0] + bc[0];
    }
}

// ---------------- K4: final (1 block, 1024 threads) --------------------------
// out: [0:18] logits, [18] intrinsic, [19] w_value, [20] m_value
__global__ void __launch_bounds__(1024)
k4_final(const float* __restrict__ hn_m, const float* __restrict__ cn_m,
         const float* __restrict__ Wmv, const float* __restrict__ states,
         const float* __restrict__ bmv, const int* __restrict__ tickp,
         float* __restrict__ out) {
    const int tid = threadIdx.x;
    const int warp = tid >> 5, lane = tid & 31;
    __shared__ float wsum[32], wsum2[32];
    __shared__ float sc[4];
    __shared__ __align__(16) float ghat_s[Dd];
    __shared__ __align__(16) float gsum[Dd];

    const int tick = *tickp;
    float acc_sq = 0.f, acc_mv = 0.f;
#pragma unroll
    for (int rep = 0; rep < 2; rep++) {
        const int i = tid + rep * 1024;
        float g0 = d_gact[i];
        float g1 = d_gact[i + Dd];
        float g2 = d_gact[i + 2 * Dd];
        float g3 = d_gact[i + 3 * Dd];
        float ig = sigm(g0), fg = sigm(g1);
        float gt = tanhf(g2), og = sigm(g3);
        float c2 = fmaf(fg, cn_m[(size_t)tick * Dd + i], ig * gt);
        float hnew = og * tanhf(c2);
        float hs = d_hsum[i] - hn_m[(size_t)tick * Dd + i] + hnew;
        float gh = hs * 0.1f;
        ghat_s[i] = gh;
        acc_sq = fmaf(gh, gh, acc_sq);
        acc_mv = fmaf(gh, Wmv[i], acc_mv);
    }
#pragma unroll
    for (int o = 16; o; o >>= 1) {
        acc_sq += __shfl_xor_sync(0xffffffffu, acc_sq, o);
        acc_mv += __shfl_xor_sync(0xffffffffu, acc_mv, o);
    }
    if (!lane) { wsum[warp] = acc_sq; wsum2[warp] = acc_mv; }
    __syncthreads();
    if (tid == 0) {
        float sa = 0.f, sb = 0.f;
#pragma unroll
        for (int q = 0; q < 32; q++) { sa += wsum[q]; sb += wsum2[q]; }
        sc[0] = 1.f / fmaxf(sqrtf(sa), 1e-12f);
        sc[1] = sb;
    }
    __syncthreads();

    const float inv_norm = sc[0];
    for (int d = tid; d < Dd; d += 1024)
        gsum[d] = fmaf(ghat_s[d], inv_norm, d_goalsum[d]);
    __syncthreads();

    if (warp < NAa) {
        float v = wdot<16>((const float4*)(d_T + (size_t)warp * Dd),
                           (const float4*)gsum, lane);
        if (!lane) out[warp] = v;
    } else if (warp == NAa) {
        const float* st = states + (size_t)Rr * Dd;
        float num = 0.f, dd = 0.f, gg = 0.f;
        for (int d = lane; d < Dd; d += 32) {
            float diff = d_s[d] - st[d];
            float go = ghat_s[d] * inv_norm;
            num = fmaf(diff, go, num);
            dd = fmaf(diff, diff, dd);
            gg = fmaf(go, go, gg);
        }
#pragma unroll
        for (int o = 16; o; o >>= 1) {
            num += __shfl_xor_sync(0xffffffffu, num, o);
            dd += __shfl_xor_sync(0xffffffffu, dd, o);
            gg += __shfl_xor_sync(0xffffffffu, gg, o);
        }
        if (!lane)
            sc[2] = num / (fmaxf(sqrtf(dd), 1e-8f) * fmaxf(sqrtf(gg), 1e-8f));
    }
    __syncthreads();
    if (tid == 0) {
        float cs = sc[2];
#pragma unroll
        for (int r = 0; r < Rr - 1; r++) cs += d_cosv[r];
        out[18] = 2048.f * cs * 0.1f;
        out[19] = d_wval;
        out[20] = sc[1] + bmv[0];
    }
}

// ---------------- launch ------------------------------------------------------
extern "C" void kernel_launch(void* const* d_in, const int* in_sizes, int n_in,
                              void* d_out, int out_size) {
    const float* x      = (const float*)d_in[0];
    const float* Wp     = (const float*)d_in[1];
    const float* bp     = (const float*)d_in[2];
    const float* Wms    = (const float*)d_in[3];
    const float* bms    = (const float*)d_in[4];
    const float* Wih_m  = (const float*)d_in[5];
    const float* Whh_m  = (const float*)d_in[6];
    const float* bih_m  = (const float*)d_in[7];
    const float* bhh_m  = (const float*)d_in[8];
    const float* hn_m   = (const float*)d_in[9];
    const float* cn_m   = (const float*)d_in[10];
    const float* Wmv    = (const float*)d_in[11];
    const float* bmv    = (const float*)d_in[12];
    const float* Wih_w  = (const float*)d_in[13];
    const float* Whh_w  = (const float*)d_in[14];
    const float* bih_w  = (const float*)d_in[15];
    const float* bhh_w  = (const float*)d_in[16];
    const float* hn_w   = (const float*)d_in[17];
    const float* cn_w   = (const float*)d_in[18];
    const float* Wphi   = (const float*)d_in[19];
    const float* Wc     = (const float*)d_in[20];
    const float* bc     = (const float*)d_in[21];
    const float* states = (const float*)d_in[22];
    const float* goals  = (const float*)d_in[23];
    const int*   tick   = (const int*)d_in[24];
    float* out = (float*)d_out;

    kS<<<272, 256>>>(x, Wp, bp, Wms, bms, hn_m, goals);
    kBig<<<2634, 256>>>(Wih_w, Whh_w, bih_w, bhh_w, hn_w, cn_w,
                        Whh_m, bih_m, bhh_m, hn_m, Wih_m, Wphi,
                        goals, states, Wc, bc, tick);
    k4_final<<<1, 1024>>>(hn_m, cn_m, Wmv, states, bmv, tick, out);
}

// round 8
// speedup vs baseline: 1.1660x; 1.1660x over previous
#include <cuda_runtime.h>
#include <math.h>

#define Dd 2048
#define Hh 1152
#define Kk 64
#define NAa 18
#define Rr 10

#define GRID 471
#define NCHUNK 1882
// chunk index map
#define S0   0      // 256 chunks: s rows (8 rows each)
#define W0   256    // 576 chunks: worker gates (2 units each)
#define HS0  832    // 8 chunks: hsum
#define GS0  840    // 8 chunks: goalsum
#define M0   848    // 1024 chunks: manager fused gates (8 rows each) [waits s]
#define T0   1872   // 8 chunks: T columns                           [waits u]
#define COSC 1880   // 1 chunk: cosines r=0..8                       [waits s]
#define WVC  1881   // 1 chunk: w_value                              [waits u]

// ---------------- scratch (device globals) ----------------------------------
__device__ __align__(16) float d_s[Dd];
__device__ __align__(16) float d_u[Hh];
__device__ __align__(16) float d_gact[4 * Dd];
__device__ __align__(16) float d_T[NAa * Dd];
__device__ __align__(16) float d_hsum[Dd];
__device__ __align__(16) float d_goalsum[Dd];
__device__ float d_cosv[Rr];
__device__ float d_wval;
__device__ int d_sdone, d_udone, d_bdone;   // zero-init; reset by epilogue

__device__ __forceinline__ float sigm(float x) { return 1.f / (1.f + expf(-x)); }

// warp dot over NIT*32 float4s (lane-strided), result on all lanes
template <int NIT>
__device__ __forceinline__ float wdot(const float4* __restrict__ a,
                                      const float4* __restrict__ b, int lane) {
    float acc = 0.f;
#pragma unroll
    for (int i = 0; i < NIT; i++) {
        float4 x = a[lane + i * 32];
        float4 y = b[lane + i * 32];
        acc = fmaf(x.x, y.x, acc);
        acc = fmaf(x.y, y.y, acc);
        acc = fmaf(x.z, y.z, acc);
        acc = fmaf(x.w, y.w, acc);
    }
#pragma unroll
    for (int o = 16; o; o >>= 1) acc += __shfl_xor_sync(0xffffffffu, acc, o);
    return acc;
}

// fused dual warp-dot: acc1 = a1·b1, acc2 = a2·b2 over 16*32 float4s each
__device__ __forceinline__ float2 wdot2(const float4* __restrict__ a1,
                                        const float4* __restrict__ b1,
                                        const float4* __restrict__ a2,
                                        const float4* __restrict__ b2,
                                        int lane) {
    float s1 = 0.f, s2 = 0.f;
#pragma unroll
    for (int i = 0; i < 16; i++) {
        float4 x1 = a1[lane + i * 32], y1 = b1[lane + i * 32];
        float4 x2 = a2[lane + i * 32], y2 = b2[lane + i * 32];
        s1 = fmaf(x1.x, y1.x, s1); s1 = fmaf(x1.y, y1.y, s1);
        s1 = fmaf(x1.z, y1.z, s1); s1 = fmaf(x1.w, y1.w, s1);
        s2 = fmaf(x2.x, y2.x, s2); s2 = fmaf(x2.y, y2.y, s2);
        s2 = fmaf(x2.z, y2.z, s2); s2 = fmaf(x2.w, y2.w, s2);
    }
#pragma unroll
    for (int o = 16; o; o >>= 1) {
        s1 += __shfl_xor_sync(0xffffffffu, s1, o);
        s2 += __shfl_xor_sync(0xffffffffu, s2, o);
    }
    return make_float2(s1, s2);
}

__device__ __forceinline__ void wait_ctr(int* ctr, int tgt) {
    if (threadIdx.x == 0) {
        volatile int* c = ctr;
        while (*c < tgt) __nanosleep(64);
        __threadfence();
    }
    __syncthreads();
}

// ---------------- the one kernel ---------------------------------------------
__global__ void __launch_bounds__(256, 4)
fun_persistent(const float* __restrict__ x, const float* __restrict__ Wp,
               const float* __restrict__ bp, const float* __restrict__ Wms,
               const float* __restrict__ bms, const float* __restrict__ Wih_m,
               const float* __restrict__ Whh_m, const float* __restrict__ bih_m,
               const float* __restrict__ bhh_m, const float* __restrict__ hn_m,
               const float* __restrict__ cn_m, const float* __restrict__ Wmv,
               const float* __restrict__ bmv, const float* __restrict__ Wih_w,
               const float* __restrict__ Whh_w, const float* __restrict__ bih_w,
               const float* __restrict__ bhh_w, const float* __restrict__ hn_w,
               const float* __restrict__ cn_w, const float* __restrict__ Wphi,
               const float* __restrict__ Wc, const float* __restrict__ bc,
               const float* __restrict__ states, const float* __restrict__ goals,
               const int* __restrict__ tickp, float* __restrict__ out) {
    const int tid = threadIdx.x;
    const int warp = tid >> 5, lane = tid & 31;
    __shared__ __align__(16) float sm[4096];   // zs / us / ghat+gsum
    __shared__ float gsh[8];
    __shared__ float red[256];
    __shared__ float sc[4];
    __shared__ int elast;

    for (int c = blockIdx.x; c < NCHUNK; c += GRID) {
        if (c < W0) {
            // ---- s chunk: z in smem, 8 s rows ----
            __syncthreads();
            float x0 = x[0], x1 = x[1];
            for (int i = tid; i < Dd; i += 256) {
                float v = fmaf(Wp[2 * i], x0, fmaf(Wp[2 * i + 1], x1, bp[i]));
                sm[i] = fmaxf(v, 0.f);
            }
            __syncthreads();
            int row = c * 8 + warp;
            float v = wdot<16>((const float4*)(Wms + (size_t)row * Dd),
                               (const float4*)sm, lane);
            if (!lane) {
                d_s[row] = fmaxf(v + bms[row], 0.f);
                __threadfence();
            }
            __syncthreads();
            if (tid == 0) atomicAdd(&d_sdone, 1);
        } else if (c < HS0) {
            // ---- worker chunk: z in smem, 2 units (8 gate rows) ----
            __syncthreads();
            float x0 = x[0], x1 = x[1];
            for (int i = tid; i < Dd; i += 256) {
                float v = fmaf(Wp[2 * i], x0, fmaf(Wp[2 * i + 1], x1, bp[i]));
                sm[i] = fmaxf(v, 0.f);
            }
            __syncthreads();
            const int unit = (c - W0) * 2 + (warp >> 2);
            const int q = warp & 3;
            const int row = unit + q * Hh;
            float a = wdot<16>((const float4*)(Wih_w + (size_t)row * Dd),
                               (const float4*)sm, lane);
            float cc = wdot<9>((const float4*)(Whh_w + (size_t)row * Hh),
                               (const float4*)hn_w, lane);
            if (!lane) gsh[warp] = a + cc + bih_w[row] + bhh_w[row];
            __syncthreads();
            if ((tid & 127) == 0) {
                const int half = tid >> 7;
                const int j = (c - W0) * 2 + half;
                const float* g = gsh + half * 4;
                float ig = sigm(g[0]), fg = sigm(g[1]);
                float g2 = tanhf(g[2]), og = sigm(g[3]);
                float c2 = fmaf(fg, cn_w[j], ig * g2);
                d_u[j] = og * tanhf(c2);
                __threadfence();
            }
            __syncthreads();
            if (tid == 0) atomicAdd(&d_udone, 1);
        } else if (c < GS0) {
            const int i = (c - HS0) * 256 + tid;
            float a = 0.f;
#pragma unroll
            for (int r = 0; r < Rr; r++) a += hn_m[(size_t)r * Dd + i];
            d_hsum[i] = a;
        } else if (c < M0) {
            const int d = (c - GS0) * 256 + tid;
            float a = 0.f;
#pragma unroll
            for (int r = 1; r < Rr; r++) a += goals[(size_t)r * Dd + d];
            d_goalsum[d] = a;
        } else if (c < T0) {
            // ---- manager fused chunk: 8 gate rows, needs s ----
            wait_ctr(&d_sdone, 256);
            const int tick = *tickp;
            const int row = (c - M0) * 8 + warp;
            float2 v = wdot2((const float4*)(Wih_m + (size_t)row * Dd),
                             (const float4*)d_s,
                             (const float4*)(Whh_m + (size_t)row * Dd),
                             (const float4*)(hn_m + (size_t)tick * Dd), lane);
            if (!lane)
                d_gact[row] = v.x + v.y + bih_m[row] + bhh_m[row];
        } else if (c < COSC) {
            // ---- T chunk: 256 d-columns, needs u ----
            wait_ctr(&d_udone, 576);
            __syncthreads();
            for (int i = tid; i < NAa * Kk; i += 256) sm[i] = d_u[i];
            __syncthreads();
            const int d = (c - T0) * 256 + tid;
            float acc[NAa];
#pragma unroll
            for (int a = 0; a < NAa; a++) acc[a] = 0.f;
            for (int k = 0; k < Kk; k++) {
                float w = Wphi[(size_t)k * Dd + d];
#pragma unroll
                for (int a = 0; a < NAa; a++)
                    acc[a] = fmaf(sm[a * Kk + k], w, acc[a]);
            }
#pragma unroll
            for (int a = 0; a < NAa; a++) d_T[(size_t)a * Dd + d] = acc[a];
        } else if (c == COSC) {
            // ---- cosines r=0..8, needs s ----
            wait_ctr(&d_sdone, 256);
            for (int r = warp; r < Rr - 1; r += 8) {
                const float* st = states + (size_t)(r + 1) * Dd;
                const float* gl = goals + (size_t)(r + 1) * Dd;
                float num = 0.f, dd = 0.f, gg = 0.f;
                for (int d = lane; d < Dd; d += 32) {
                    float diff = d_s[d] - st[d];
                    float go = gl[d];
                    num = fmaf(diff, go, num);
                    dd = fmaf(diff, diff, dd);
                    gg = fmaf(go, go, gg);
                }
#pragma unroll
                for (int o = 16; o; o >>= 1) {
                    num += __shfl_xor_sync(0xffffffffu, num, o);
                    dd += __shfl_xor_sync(0xffffffffu, dd, o);
                    gg += __shfl_xor_sync(0xffffffffu, gg, o);
                }
                if (!lane)
                    d_cosv[r] = num / (fmaxf(sqrtf(dd), 1e-8f) *
                                       fmaxf(sqrtf(gg), 1e-8f));
            }
        } else {
            // ---- w_value, needs u ----
            wait_ctr(&d_udone, 576);
            float wv = 0.f;
            for (int j = tid; j < Hh; j += 256) wv = fmaf(d_u[j], Wc[j], wv);
            red[tid] = wv;
            __syncthreads();
            for (int s = 128; s; s >>= 1) {
                if (tid < s) red[tid] += red[tid + s];
                __syncthreads();
            }
            if (tid == 0) d_wval = red[0] + bc[0];
        }
    }

    // ---- block done; last block runs the epilogue ----
    __threadfence();
    if (tid == 0) {
        int p = atomicAdd(&d_bdone, 1);
        elast = (p == GRID - 1);
    }
    __syncthreads();
    if (!elast) return;
    __threadfence();

    // epilogue: manager LSTM pointwise -> ghat, norms, gsum, logits, outputs
    const int tick = *tickp;
    float* ghat = sm;          // [0,2048)
    float* gsum = sm + 2048;   // [2048,4096)
    float acc_sq = 0.f, acc_mv = 0.f;
#pragma unroll
    for (int rep = 0; rep < 8; rep++) {
        const int i = tid + rep * 256;
        float g0 = d_gact[i];
        float g1 = d_gact[i + Dd];
        float g2 = d_gact[i + 2 * Dd];
        float g3 = d_gact[i + 3 * Dd];
        float ig = sigm(g0), fg = sigm(g1);
        float gt = tanhf(g2), og = sigm(g3);
        float c2 = fmaf(fg, cn_m[(size_t)tick * Dd + i], ig * gt);
        float hnew = og * tanhf(c2);
        float hs = d_hsum[i] - hn_m[(size_t)tick * Dd + i] + hnew;
        float gh = hs * 0.1f;
        ghat[i] = gh;
        acc_sq = fmaf(gh, gh, acc_sq);
        acc_mv = fmaf(gh, Wmv[i], acc_mv);
    }
#pragma unroll
    for (int o = 16; o; o >>= 1) {
        acc_sq += __shfl_xor_sync(0xffffffffu, acc_sq, o);
        acc_mv += __shfl_xor_sync(0xffffffffu, acc_mv, o);
    }
    if (!lane) { red[warp] = acc_sq; red[warp + 8] = acc_mv; }
    __syncthreads();
    if (tid == 0) {
        float sa = 0.f, sb = 0.f;
#pragma unroll
        for (int q = 0; q < 8; q++) { sa += red[q]; sb += red[q + 8]; }
        sc[0] = 1.f / fmaxf(sqrtf(sa), 1e-12f);
        sc[1] = sb;
    }
    __syncthreads();
    const float inv_norm = sc[0];
    for (int d = tid; d < Dd; d += 256)
        gsum[d] = fmaf(ghat[d], inv_norm, d_goalsum[d]);
    __syncthreads();

    for (int a = warp; a < NAa; a += 8) {
        float v = wdot<16>((const float4*)(d_T + (size_t)a * Dd),
                           (const float4*)gsum, lane);
        if (!lane) out[a] = v;
    }
    if (warp == 0) {
        // last cosine (r = 9, goal = g)
        const float* st = states + (size_t)Rr * Dd;
        float num = 0.f, dd = 0.f, gg = 0.f;
        for (int d = lane; d < Dd; d += 32) {
            float diff = d_s[d] - st[d];
            float go = ghat[d] * inv_norm;
            num = fmaf(diff, go, num);
            dd = fmaf(diff, diff, dd);
            gg = fmaf(go, go, gg);
        }
#pragma unroll
        for (int o = 16; o; o >>= 1) {
            num += __shfl_xor_sync(0xffffffffu, num, o);
            dd += __shfl_xor_sync(0xffffffffu, dd, o);
            gg += __shfl_xor_sync(0xffffffffu, gg, o);
        }
        if (!lane)
            sc[2] = num / (fmaxf(sqrtf(dd), 1e-8f) * fmaxf(sqrtf(gg), 1e-8f));
    }
    __syncthreads();
    if (tid == 0) {
        float cs = sc[2];
#pragma unroll
        for (int r = 0; r < Rr - 1; r++) cs += d_cosv[r];
        out[18] = 2048.f * cs * 0.1f;
        out[19] = d_wval;
        out[20] = sc[1] + bmv[0];
        // reset flags for next graph replay
        d_sdone = 0;
        d_udone = 0;
        d_bdone = 0;
    }
}

// ---------------- launch ------------------------------------------------------
extern "C" void kernel_launch(void* const* d_in, const int* in_sizes, int n_in,
                              void* d_out, int out_size) {
    const float* x      = (const float*)d_in[0];
    const float* Wp     = (const float*)d_in[1];
    const float* bp     = (const float*)d_in[2];
    const float* Wms    = (const float*)d_in[3];
    const float* bms    = (const float*)d_in[4];
    const float* Wih_m  = (const float*)d_in[5];
    const float* Whh_m  = (const float*)d_in[6];
    const float* bih_m  = (const float*)d_in[7];
    const float* bhh_m  = (const float*)d_in[8];
    const float* hn_m   = (const float*)d_in[9];
    const float* cn_m   = (const float*)d_in[10];
    const float* Wmv    = (const float*)d_in[11];
    const float* bmv    = (const float*)d_in[12];
    const float* Wih_w  = (const float*)d_in[13];
    const float* Whh_w  = (const float*)d_in[14];
    const float* bih_w  = (const float*)d_in[15];
    const float* bhh_w  = (const float*)d_in[16];
    const float* hn_w   = (const float*)d_in[17];
    const float* cn_w   = (const float*)d_in[18];
    const float* Wphi   = (const float*)d_in[19];
    const float* Wc     = (const float*)d_in[20];
    const float* bc     = (const float*)d_in[21];
    const float* states = (const float*)d_in[22];
    const float* goals  = (const float*)d_in[23];
    const int*   tick   = (const int*)d_in[24];
    float* out = (float*)d_out;

    fun_persistent<<<GRID, 256>>>(x, Wp, bp, Wms, bms, Wih_m, Whh_m, bih_m,
                                  bhh_m, hn_m, cn_m, Wmv, bmv, Wih_w, Whh_w,
                                  bih_w, bhh_w, hn_w, cn_w, Wphi, Wc, bc,
                                  states, goals, tick, out);
}